// round 11
// baseline (speedup 1.0000x reference)
#include <cuda_runtime.h>
#include <math.h>

namespace cfg {
constexpr int Bb = 8, Td = 10, T0d = 12, Nn = 3000, Cc = 64, Wd = 8;
constexpr int BC = Bb * Cc;            // 512
constexpr int MCONV = Bb * Wd * Nn;    // 192000 = 1500*128
}
using namespace cfg;

// ---------------- scratch (device globals; no allocations) ----------------
__device__ float g_xr[Td * Nn * BC];
__device__ float g_wingY[Wd * Nn * BC];
__device__ float g_ybuf[Wd * Nn * BC];
__device__ float g_dbuf[Wd * Nn * BC];
__device__ float g_maxbuf[Wd * Nn * BC];
__device__ float g_zbuf[Wd * Bb * Nn * 128];
__device__ float g_c1buf[MCONV * 128];
__device__ float g_c2buf[MCONV * 128];
__device__ float g_w1r[192 * 128];
__device__ float g_w2r[320 * 128];

__device__ __forceinline__ unsigned f2t(float x) {
    unsigned u; asm("cvt.rna.tf32.f32 %0, %1;" : "=r"(u) : "f"(x)); return u;
}
__device__ __forceinline__ float sigm(float x) { return 1.f / (1.f + expf(-x)); }
__device__ __forceinline__ void mma8(float* c, const unsigned* a, unsigned b0, unsigned b1) {
    asm volatile("mma.sync.aligned.m16n8k8.row.col.f32.tf32.tf32.f32 "
                 "{%0,%1,%2,%3},{%4,%5,%6,%7},{%8,%9},{%0,%1,%2,%3};\n"
                 : "+f"(c[0]), "+f"(c[1]), "+f"(c[2]), "+f"(c[3])
                 : "r"(a[0]), "r"(a[1]), "r"(a[2]), "r"(a[3]), "r"(b0), "r"(b1));
}

// ---------------- prep ----------------
__global__ void prep_x(const float* __restrict__ data, const float* __restrict__ temb,
                       const float* __restrict__ semb) {
    int idx = blockIdx.x * blockDim.x + threadIdx.x;
    if (idx >= Td * Nn * BC / 4) return;
    int c4 = idx & 15, rem = idx >> 4;
    int b = rem & 7; rem >>= 3;
    int n = rem % Nn, t = rem / Nn;
    float4 dv = *(const float4*)(data + ((size_t)((b * Td + t) * Nn + n)) * 64 + c4 * 4);
    float4 tv = *(const float4*)(temb + t * 64 + c4 * 4);
    float4 sv = *(const float4*)(semb + (size_t)n * 64 + c4 * 4);
    float4 o = {dv.x + tv.x + sv.x, dv.y + tv.y + sv.y, dv.z + tv.z + sv.z, dv.w + tv.w + sv.w};
    *(float4*)(g_xr + (size_t)idx * 4) = o;
}

__global__ void prep_w(const float* __restrict__ w1, const float* __restrict__ w2) {
    int idx = blockIdx.x * blockDim.x + threadIdx.x;
    if (idx < 192 * 128) {
        int oc = idx & 127, kk = idx >> 7, c = kk & 63, ms = kk >> 6;
        g_w1r[idx] = w1[(oc * 64 + c) * 3 + ms];
    } else if (idx < 192 * 128 + 320 * 128) {
        int j = idx - 192 * 128;
        int oc = j & 127, kk = j >> 7, c = kk & 63, ms = kk >> 6;
        g_w2r[j] = w2[(oc * 64 + c) * 5 + ms];
    }
}

// ---------------- tf32 GEMM: C = A(MxK) @ B(KxN) [+Add], 128x128x16 tiles ----------------
// CONV=true: A rows are im2col of D[b][t][n][64], row m=(b*Wd+w)*Nn+n, col kk=ms*64+c.
template <bool CONV>
__global__ __launch_bounds__(256) void gemm_tf32(
    const float* __restrict__ A, long long lda, long long sAo, long long sAi,
    const float* __restrict__ Bm, long long ldb, long long sBo, long long sBi,
    float* __restrict__ Cm, long long ldc, long long sCo, long long sCi,
    const float* __restrict__ AddP, long long sDo, long long sDi,
    int M, int Kd, int binner, int Tdim) {
    __shared__ __align__(16) unsigned As[2][16][132];
    __shared__ __align__(16) unsigned Bs[2][16][132];

    const int z = blockIdx.z, zo = z / binner, zi = z - zo * binner;
    A += zo * sAo + zi * sAi;
    Bm += zo * sBo + zi * sBi;
    Cm += zo * sCo + zi * sCi;
    const float* Ad = AddP ? (AddP + zo * sDo + zi * sDi) : nullptr;

    const int tid = threadIdx.x, lane = tid & 31, warp = tid >> 5;
    const int wm = warp >> 1, wn = warp & 1;
    const int m0 = blockIdx.y * 128, n0 = blockIdx.x * 128;
    const int aRow = tid >> 2, aKq = tid & 3;
    const int bKk = tid >> 5, bNq = tid & 31;

    long long baseA[2];
    if (CONV) {
#pragma unroll
        for (int it = 0; it < 2; ++it) {
            int m = m0 + aRow + it * 64;
            int b = m / (Wd * Nn), rem = m - b * (Wd * Nn);
            int w = rem / Nn, n = rem - w * Nn;
            baseA[it] = ((long long)((b * Tdim + w) * Nn + n)) * 64;
        }
    }

    float acc[2][8][4];
#pragma unroll
    for (int i = 0; i < 2; i++)
#pragma unroll
        for (int j = 0; j < 8; j++)
#pragma unroll
            for (int q = 0; q < 4; q++) acc[i][j][q] = 0.f;

    float aReg[2][4], bReg[2][4];
    const int ntiles = (Kd + 15) >> 4;

    auto LOAD = [&](int kt) {
        const int k0 = kt << 4;
        const int kg = k0 + aKq * 4;
#pragma unroll
        for (int it = 0; it < 2; ++it) {
            if (CONV) {
                const int ms = kg >> 6, cc = kg & 63;
                float4 v = *(const float4*)(A + baseA[it] + (long long)ms * (Nn * 64) + cc);
                aReg[it][0] = v.x; aReg[it][1] = v.y; aReg[it][2] = v.z; aReg[it][3] = v.w;
            } else {
                const int mg = m0 + aRow + it * 64;
                if (mg < M && kg + 4 <= Kd) {
                    float4 v = *(const float4*)(A + (long long)mg * lda + kg);
                    aReg[it][0] = v.x; aReg[it][1] = v.y; aReg[it][2] = v.z; aReg[it][3] = v.w;
                } else {
#pragma unroll
                    for (int j = 0; j < 4; j++)
                        aReg[it][j] = (mg < M && kg + j < Kd) ? A[(long long)mg * lda + kg + j] : 0.f;
                }
            }
        }
#pragma unroll
        for (int it = 0; it < 2; ++it) {
            const int kr = k0 + bKk + it * 8;
            if (kr < Kd) {
                float4 v = *(const float4*)(Bm + (long long)kr * ldb + n0 + bNq * 4);
                bReg[it][0] = v.x; bReg[it][1] = v.y; bReg[it][2] = v.z; bReg[it][3] = v.w;
            } else {
                bReg[it][0] = bReg[it][1] = bReg[it][2] = bReg[it][3] = 0.f;
            }
        }
    };
    auto STOREs = [&](int buf) {
#pragma unroll
        for (int it = 0; it < 2; ++it) {
            const int r = aRow + it * 64;
#pragma unroll
            for (int j = 0; j < 4; j++) As[buf][aKq * 4 + j][r] = f2t(aReg[it][j]);
        }
#pragma unroll
        for (int it = 0; it < 2; ++it) {
            uint4 p = {f2t(bReg[it][0]), f2t(bReg[it][1]), f2t(bReg[it][2]), f2t(bReg[it][3])};
            *(uint4*)&Bs[buf][bKk + it * 8][bNq * 4] = p;
        }
    };
    auto COMP = [&](int buf) {
#pragma unroll
        for (int ks = 0; ks < 2; ++ks) {
            const int kb = ks * 8 + (lane & 3);
            unsigned afr[2][4];
#pragma unroll
            for (int mt = 0; mt < 2; ++mt) {
                const int mr = wm * 32 + mt * 16 + (lane >> 2);
                afr[mt][0] = As[buf][kb][mr];
                afr[mt][1] = As[buf][kb][mr + 8];
                afr[mt][2] = As[buf][kb + 4][mr];
                afr[mt][3] = As[buf][kb + 4][mr + 8];
            }
#pragma unroll
            for (int nt = 0; nt < 8; ++nt) {
                const int nc = wn * 64 + nt * 8 + (lane >> 2);
                const unsigned b0 = Bs[buf][kb][nc];
                const unsigned b1 = Bs[buf][kb + 4][nc];
                mma8(acc[0][nt], afr[0], b0, b1);
                mma8(acc[1][nt], afr[1], b0, b1);
            }
        }
    };

    LOAD(0);
    STOREs(0);
    __syncthreads();
    for (int kt = 0; kt < ntiles; ++kt) {
        const int buf = kt & 1;
        if (kt + 1 < ntiles) LOAD(kt + 1);
        COMP(buf);
        if (kt + 1 < ntiles) STOREs(buf ^ 1);
        __syncthreads();
    }

#pragma unroll
    for (int mt = 0; mt < 2; ++mt) {
#pragma unroll
        for (int half = 0; half < 2; ++half) {
            const int mr = m0 + wm * 32 + mt * 16 + (lane >> 2) + half * 8;
            if (mr >= M) continue;
#pragma unroll
            for (int nt = 0; nt < 8; ++nt) {
                const int nc = n0 + wn * 64 + nt * 8 + (lane & 3) * 2;
                float v0 = acc[mt][nt][half * 2 + 0];
                float v1 = acc[mt][nt][half * 2 + 1];
                if (Ad) {
                    float2 av = *(const float2*)(Ad + (long long)mr * ldc + nc);
                    v0 += av.x; v1 += av.y;
                }
                float2 ov = {v0, v1};
                *(float2*)(Cm + (long long)mr * ldc + nc) = ov;
            }
        }
    }
}

// ---------------- elementwise ----------------
__global__ void conv_epi(const float* __restrict__ c1b, const float* __restrict__ c2b,
                         float* __restrict__ out) {
    int idx = blockIdx.x * blockDim.x + threadIdx.x;
    if (idx >= MCONV * 64) return;
    int c = idx & 63;
    long long r = idx >> 6;
    float L1 = g_c1buf[r * 128 + c] + c1b[c];
    float R1 = g_c1buf[r * 128 + 64 + c] + c1b[64 + c];
    float L2 = g_c2buf[r * 128 + c] + c2b[c];
    float R2 = g_c2buf[r * 128 + 64 + c] + c2b[64 + c];
    out[idx] = sigm(L1) * R1 + sigm(L2) * R2;
}

__global__ void glu_epi(const float* __restrict__ gb, int k) {
    int idx = blockIdx.x * blockDim.x + threadIdx.x;
    if (idx >= Wd * Bb * Nn * 64) return;
    int c = idx & 63;
    int r = idx >> 6;                       // (w*8+b)*N + n
    int wb = r / Nn, n = r - wb * Nn;
    int w = wb >> 3, b = wb & 7;
    float zl = g_zbuf[(long long)r * 128 + c] + gb[(w * 3 + k) * 128 + c];
    float zr = g_zbuf[(long long)r * 128 + 64 + c] + gb[(w * 3 + k) * 128 + 64 + c];
    float d = zl * sigm(zr);
    long long di = (long long)(w * Nn + n) * 512 + b * 64 + c;
    g_dbuf[di] = d;
    g_maxbuf[di] = (k == 0) ? d : fmaxf(g_maxbuf[di], d);
}

__global__ void final_add(float* __restrict__ out) {
    int idx = blockIdx.x * blockDim.x + threadIdx.x;
    if (idx >= Bb * Wd * Nn * 64) return;
    int c = idx & 63;
    int r = idx >> 6;                       // (b*W+w)*N + n
    int bw = r / Nn, n = r - bw * Nn;
    int w = bw & 7, b = bw >> 3;
    long long mi = (long long)(w * Nn + n) * 512 + b * 64 + c;
    long long xi = (long long)((w + 2) * Nn + n) * 512 + b * 64 + c;
    out[idx] += g_maxbuf[mi] + g_xr[xi];
}

// ---------------- launch ----------------
extern "C" void kernel_launch(void* const* d_in, const int* in_sizes, int n_in,
                              void* d_out, int out_size) {
    const float* od   = (const float*)d_in[0];
    const float* data = (const float*)d_in[1];
    const float* adj  = (const float*)d_in[2];
    const float* w1   = (const float*)d_in[3];
    const float* b1   = (const float*)d_in[4];
    const float* w2   = (const float*)d_in[5];
    const float* b2   = (const float*)d_in[6];
    const float* temb = (const float*)d_in[7];
    const float* semb = (const float*)d_in[8];
    const float* gw   = (const float*)d_in[9];
    const float* gb   = (const float*)d_in[10];
    float* out = (float*)d_out;

    float *xr, *wingY, *ybuf, *dbuf, *zbuf, *c1buf, *c2buf, *w1r, *w2r;
    cudaGetSymbolAddress((void**)&xr, g_xr);
    cudaGetSymbolAddress((void**)&wingY, g_wingY);
    cudaGetSymbolAddress((void**)&ybuf, g_ybuf);
    cudaGetSymbolAddress((void**)&dbuf, g_dbuf);
    cudaGetSymbolAddress((void**)&zbuf, g_zbuf);
    cudaGetSymbolAddress((void**)&c1buf, g_c1buf);
    cudaGetSymbolAddress((void**)&c2buf, g_c2buf);
    cudaGetSymbolAddress((void**)&w1r, g_w1r);
    cudaGetSymbolAddress((void**)&w2r, g_w2r);

    const long long NB = (long long)Nn * 512;   // per-window row block in xr layout

    prep_x<<<15000, 256>>>(data, temb, semb);
    prep_w<<<256, 256>>>(w1, w2);

    // convs as implicit-im2col GEMMs -> pre-activation buffers
    gemm_tf32<true><<<dim3(1, 1500, 1), 256>>>(
        data, 0, 0, 0, w1r, 128, 0, 0, c1buf, 128, 0, 0,
        nullptr, 0, 0, MCONV, 192, 1, Td);
    gemm_tf32<true><<<dim3(1, 1500, 1), 256>>>(
        od, 0, 0, 0, w2r, 128, 0, 0, c2buf, 128, 0, 0,
        nullptr, 0, 0, MCONV, 320, 1, T0d);
    conv_epi<<<48000, 256>>>(b1, b2, out);

    // wingY[w] = adj[:, :2N] @ xr[w*N : w*N+2N]   (z = w)
    gemm_tf32<false><<<dim3(4, 24, 8), 256>>>(
        adj, 3 * Nn, 0, 0, xr, 512, NB, 0, wingY, 512, NB, 0,
        nullptr, 0, 0, Nn, 2 * Nn, 1, 0);

    for (int k = 0; k < 3; ++k) {
        const float* dsrc = (k == 0) ? (xr + 2 * NB) : dbuf;
        // y = adj[:, 2N:] @ d + wingY
        gemm_tf32<false><<<dim3(4, 24, 8), 256>>>(
            adj + 2 * Nn, 3 * Nn, 0, 0, dsrc, 512, NB, 0, ybuf, 512, NB, 0,
            wingY, NB, 0, Nn, Nn, 1, 0);
        // z = y @ glu_w[w,k]   batched over (w,b): z = w*8+b
        gemm_tf32<false><<<dim3(1, 24, 64), 256>>>(
            ybuf, 512, NB, 64,
            gw + k * 64 * 128, 128, 3 * 64 * 128, 0,
            zbuf, 128, (long long)Bb * Nn * 128, (long long)Nn * 128,
            nullptr, 0, 0, Nn, 64, 8, 0);
        glu_epi<<<48000, 256>>>(gb, k);
    }

    final_add<<<48000, 256>>>(out);
}

// round 12
// speedup vs baseline: 1.2703x; 1.2703x over previous
#include <cuda_runtime.h>
#include <math.h>

namespace cfg {
constexpr int Bb = 8, Td = 10, T0d = 12, Nn = 3000, Cc = 64, Wd = 8;
constexpr int BC = Bb * Cc;            // 512
constexpr int MCONV = Bb * Wd * Nn;    // 192000 = 1500*128
}
using namespace cfg;

// ---------------- scratch (device globals; no allocations) ----------------
__device__ float g_xr[Td * Nn * BC];
__device__ float g_wingY[Wd * Nn * BC];
__device__ float g_ybuf[Wd * Nn * BC];
__device__ float g_d0[Wd * Nn * BC];
__device__ float g_d1[Wd * Nn * BC];
__device__ float g_d2[Wd * Nn * BC];
__device__ float g_c1buf[MCONV * 128];
__device__ float g_c2buf[MCONV * 128];
__device__ float g_w1r[192 * 128];
__device__ float g_w2r[320 * 128];
__device__ float g_gwr[Wd * 3 * 64 * 128];
__device__ float g_gbr[Wd * 3 * 128];

__device__ __forceinline__ unsigned f2t(float x) {
    unsigned u; asm("cvt.rna.tf32.f32 %0, %1;" : "=r"(u) : "f"(x)); return u;
}
__device__ __forceinline__ float sigm(float x) { return 1.f / (1.f + expf(-x)); }
__device__ __forceinline__ void mma8(float* c, const unsigned* a, unsigned b0, unsigned b1) {
    asm volatile("mma.sync.aligned.m16n8k8.row.col.f32.tf32.tf32.f32 "
                 "{%0,%1,%2,%3},{%4,%5,%6,%7},{%8,%9},{%0,%1,%2,%3};\n"
                 : "+f"(c[0]), "+f"(c[1]), "+f"(c[2]), "+f"(c[3])
                 : "r"(a[0]), "r"(a[1]), "r"(a[2]), "r"(a[3]), "r"(b0), "r"(b1));
}

// ---------------- prep ----------------
__global__ void prep_x(const float* __restrict__ data, const float* __restrict__ temb,
                       const float* __restrict__ semb) {
    int idx = blockIdx.x * blockDim.x + threadIdx.x;
    if (idx >= Td * Nn * BC / 4) return;
    int c4 = idx & 15, rem = idx >> 4;
    int b = rem & 7; rem >>= 3;
    int n = rem % Nn, t = rem / Nn;
    float4 dv = *(const float4*)(data + ((size_t)((b * Td + t) * Nn + n)) * 64 + c4 * 4);
    float4 tv = *(const float4*)(temb + t * 64 + c4 * 4);
    float4 sv = *(const float4*)(semb + (size_t)n * 64 + c4 * 4);
    float4 o = {dv.x + tv.x + sv.x, dv.y + tv.y + sv.y, dv.z + tv.z + sv.z, dv.w + tv.w + sv.w};
    *(float4*)(g_xr + (size_t)idx * 4) = o;
}

__global__ void prep_w(const float* __restrict__ w1, const float* __restrict__ w2) {
    int idx = blockIdx.x * blockDim.x + threadIdx.x;
    if (idx < 192 * 128) {
        int oc = idx & 127, kk = idx >> 7, c = kk & 63, ms = kk >> 6;
        g_w1r[idx] = w1[(oc * 64 + c) * 3 + ms];
    } else if (idx < 192 * 128 + 320 * 128) {
        int j = idx - 192 * 128;
        int oc = j & 127, kk = j >> 7, c = kk & 63, ms = kk >> 6;
        g_w2r[j] = w2[(oc * 64 + c) * 5 + ms];
    }
}

// permute glu weights/bias so that (lhs,rhs) gate pairs are adjacent columns:
// new col j -> old col (j>>1) + (j&1)*64
__global__ void prep_glu(const float* __restrict__ gw, const float* __restrict__ gb) {
    int idx = blockIdx.x * blockDim.x + threadIdx.x;
    const int NW = Wd * 3 * 64 * 128;
    if (idx < NW) {
        int j = idx & 127, rc = idx >> 7;  // rc = (w*3+k)*64 + c
        g_gwr[idx] = gw[(size_t)rc * 128 + (j >> 1) + (j & 1) * 64];
    } else if (idx < NW + Wd * 3 * 128) {
        int t = idx - NW;
        int j = t & 127, wk = t >> 7;
        g_gbr[t] = gb[wk * 128 + (j >> 1) + (j & 1) * 64];
    }
}

// ---------------- tf32 GEMM: C = A(MxK) @ B(KxN), 128x128x16 tiles ----------------
// MODE 0: plain (+Add if AddP)          MODE 1: conv im2col A-gather
// MODE 2: GLU epilogue: pairs (zl,zr) in adjacent cols; d = (zl+bl)*sigm(zr+br),
//         written at col nc>>1 (bias from AddP, per-block).
template <int MODE>
__global__ __launch_bounds__(256) void gemm_tf32(
    const float* __restrict__ A, long long lda, long long sAo, long long sAi,
    const float* __restrict__ Bm, long long ldb, long long sBo, long long sBi,
    float* __restrict__ Cm, long long ldc, long long sCo, long long sCi,
    const float* __restrict__ AddP, long long sDo, long long sDi,
    int M, int Kd, int binner, int Tdim) {
    // As: [m][k] stride 20 -> loads bank = (20g+q) mod 32 conflict-free, STS.128 stores
    // Bs: [k][n] stride 136 -> loads bank = (8q+g) mod 32 conflict-free, STS.128 stores
    __shared__ __align__(16) unsigned As[2][128][20];
    __shared__ __align__(16) unsigned Bs[2][16][136];

    const int z = blockIdx.z, zo = z / binner, zi = z - zo * binner;
    A += zo * sAo + zi * sAi;
    Bm += zo * sBo + zi * sBi;
    Cm += zo * sCo + zi * sCi;
    const float* Ad = AddP ? (AddP + zo * sDo + zi * sDi) : nullptr;

    const int tid = threadIdx.x, lane = tid & 31, warp = tid >> 5;
    const int wm = warp >> 1, wn = warp & 1;
    const int m0 = blockIdx.y * 128, n0 = blockIdx.x * 128;
    const int aRow = tid >> 2, aKq = tid & 3;
    const int bKk = tid >> 5, bNq = tid & 31;

    long long baseA[2];
    if (MODE == 1) {
#pragma unroll
        for (int it = 0; it < 2; ++it) {
            int m = m0 + aRow + it * 64;
            int b = m / (Wd * Nn), rem = m - b * (Wd * Nn);
            int w = rem / Nn, n = rem - w * Nn;
            baseA[it] = ((long long)((b * Tdim + w) * Nn + n)) * 64;
        }
    }

    float acc[2][8][4];
#pragma unroll
    for (int i = 0; i < 2; i++)
#pragma unroll
        for (int j = 0; j < 8; j++)
#pragma unroll
            for (int q = 0; q < 4; q++) acc[i][j][q] = 0.f;

    float aReg[2][4], bReg[2][4];
    const int ntiles = (Kd + 15) >> 4;

    auto LOAD = [&](int kt) {
        const int k0 = kt << 4;
        const int kg = k0 + aKq * 4;
#pragma unroll
        for (int it = 0; it < 2; ++it) {
            if (MODE == 1) {
                const int ms = kg >> 6, cc = kg & 63;
                float4 v = *(const float4*)(A + baseA[it] + (long long)ms * (Nn * 64) + cc);
                aReg[it][0] = v.x; aReg[it][1] = v.y; aReg[it][2] = v.z; aReg[it][3] = v.w;
            } else {
                const int mg = m0 + aRow + it * 64;
                if (mg < M && kg + 4 <= Kd) {
                    float4 v = *(const float4*)(A + (long long)mg * lda + kg);
                    aReg[it][0] = v.x; aReg[it][1] = v.y; aReg[it][2] = v.z; aReg[it][3] = v.w;
                } else {
#pragma unroll
                    for (int j = 0; j < 4; j++)
                        aReg[it][j] = (mg < M && kg + j < Kd) ? A[(long long)mg * lda + kg + j] : 0.f;
                }
            }
        }
#pragma unroll
        for (int it = 0; it < 2; ++it) {
            const int kr = k0 + bKk + it * 8;
            if (kr < Kd) {
                float4 v = *(const float4*)(Bm + (long long)kr * ldb + n0 + bNq * 4);
                bReg[it][0] = v.x; bReg[it][1] = v.y; bReg[it][2] = v.z; bReg[it][3] = v.w;
            } else {
                bReg[it][0] = bReg[it][1] = bReg[it][2] = bReg[it][3] = 0.f;
            }
        }
    };
    auto STOREs = [&](int buf) {
#pragma unroll
        for (int it = 0; it < 2; ++it) {
            uint4 p = {f2t(aReg[it][0]), f2t(aReg[it][1]), f2t(aReg[it][2]), f2t(aReg[it][3])};
            *(uint4*)&As[buf][aRow + it * 64][aKq * 4] = p;
        }
#pragma unroll
        for (int it = 0; it < 2; ++it) {
            uint4 p = {f2t(bReg[it][0]), f2t(bReg[it][1]), f2t(bReg[it][2]), f2t(bReg[it][3])};
            *(uint4*)&Bs[buf][bKk + it * 8][bNq * 4] = p;
        }
    };
    auto COMP = [&](int buf) {
#pragma unroll
        for (int ks = 0; ks < 2; ++ks) {
            const int kb = ks * 8 + (lane & 3);
            unsigned afr[2][4];
#pragma unroll
            for (int mt = 0; mt < 2; ++mt) {
                const int mr = wm * 32 + mt * 16 + (lane >> 2);
                afr[mt][0] = As[buf][mr][kb];
                afr[mt][1] = As[buf][mr + 8][kb];
                afr[mt][2] = As[buf][mr][kb + 4];
                afr[mt][3] = As[buf][mr + 8][kb + 4];
            }
#pragma unroll
            for (int nt = 0; nt < 8; ++nt) {
                const int nc = wn * 64 + nt * 8 + (lane >> 2);
                const unsigned b0 = Bs[buf][kb][nc];
                const unsigned b1 = Bs[buf][kb + 4][nc];
                mma8(acc[0][nt], afr[0], b0, b1);
                mma8(acc[1][nt], afr[1], b0, b1);
            }
        }
    };

    LOAD(0);
    STOREs(0);
    __syncthreads();
    for (int kt = 0; kt < ntiles; ++kt) {
        const int buf = kt & 1;
        if (kt + 1 < ntiles) LOAD(kt + 1);
        COMP(buf);
        if (kt + 1 < ntiles) STOREs(buf ^ 1);
        __syncthreads();
    }

#pragma unroll
    for (int mt = 0; mt < 2; ++mt) {
#pragma unroll
        for (int half = 0; half < 2; ++half) {
            const int mr = m0 + wm * 32 + mt * 16 + (lane >> 2) + half * 8;
            if (mr >= M) continue;
#pragma unroll
            for (int nt = 0; nt < 8; ++nt) {
                const int nc = n0 + wn * 64 + nt * 8 + (lane & 3) * 2;
                float v0 = acc[mt][nt][half * 2 + 0];
                float v1 = acc[mt][nt][half * 2 + 1];
                if (MODE == 2) {
                    float2 bb = *(const float2*)(Ad + nc);
                    float d = (v0 + bb.x) * sigm(v1 + bb.y);
                    Cm[(long long)mr * ldc + (nc >> 1)] = d;
                } else {
                    if (Ad) {
                        float2 av = *(const float2*)(Ad + (long long)mr * ldc + nc);
                        v0 += av.x; v1 += av.y;
                    }
                    float2 ov = {v0, v1};
                    *(float2*)(Cm + (long long)mr * ldc + nc) = ov;
                }
            }
        }
    }
}

// ---------------- elementwise ----------------
__global__ void conv_epi(const float* __restrict__ c1b, const float* __restrict__ c2b,
                         float* __restrict__ out) {
    int idx = blockIdx.x * blockDim.x + threadIdx.x;
    if (idx >= MCONV * 64) return;
    int c = idx & 63;
    long long r = idx >> 6;
    float L1 = g_c1buf[r * 128 + c] + c1b[c];
    float R1 = g_c1buf[r * 128 + 64 + c] + c1b[64 + c];
    float L2 = g_c2buf[r * 128 + c] + c2b[c];
    float R2 = g_c2buf[r * 128 + 64 + c] + c2b[64 + c];
    out[idx] = sigm(L1) * R1 + sigm(L2) * R2;
}

__global__ void final_add(float* __restrict__ out) {
    int idx = blockIdx.x * blockDim.x + threadIdx.x;
    if (idx >= Bb * Wd * Nn * 64) return;
    int c = idx & 63;
    int r = idx >> 6;                       // (b*W+w)*N + n
    int bw = r / Nn, n = r - bw * Nn;
    int w = bw & 7, b = bw >> 3;
    long long mi = (long long)(w * Nn + n) * 512 + b * 64 + c;
    long long xi = (long long)((w + 2) * Nn + n) * 512 + b * 64 + c;
    float mx = fmaxf(fmaxf(g_d0[mi], g_d1[mi]), g_d2[mi]);
    out[idx] += mx + g_xr[xi];
}

// ---------------- launch ----------------
extern "C" void kernel_launch(void* const* d_in, const int* in_sizes, int n_in,
                              void* d_out, int out_size) {
    const float* od   = (const float*)d_in[0];
    const float* data = (const float*)d_in[1];
    const float* adj  = (const float*)d_in[2];
    const float* w1   = (const float*)d_in[3];
    const float* b1   = (const float*)d_in[4];
    const float* w2   = (const float*)d_in[5];
    const float* b2   = (const float*)d_in[6];
    const float* temb = (const float*)d_in[7];
    const float* semb = (const float*)d_in[8];
    const float* gw   = (const float*)d_in[9];
    const float* gb   = (const float*)d_in[10];
    float* out = (float*)d_out;

    float *xr, *wingY, *ybuf, *c1buf, *c2buf, *w1r, *w2r, *gwr, *gbr;
    float* dK[3];
    cudaGetSymbolAddress((void**)&xr, g_xr);
    cudaGetSymbolAddress((void**)&wingY, g_wingY);
    cudaGetSymbolAddress((void**)&ybuf, g_ybuf);
    cudaGetSymbolAddress((void**)&dK[0], g_d0);
    cudaGetSymbolAddress((void**)&dK[1], g_d1);
    cudaGetSymbolAddress((void**)&dK[2], g_d2);
    cudaGetSymbolAddress((void**)&c1buf, g_c1buf);
    cudaGetSymbolAddress((void**)&c2buf, g_c2buf);
    cudaGetSymbolAddress((void**)&w1r, g_w1r);
    cudaGetSymbolAddress((void**)&w2r, g_w2r);
    cudaGetSymbolAddress((void**)&gwr, g_gwr);
    cudaGetSymbolAddress((void**)&gbr, g_gbr);

    const long long NB = (long long)Nn * 512;   // per-window row block in xr layout

    prep_x<<<15000, 256>>>(data, temb, semb);
    prep_w<<<256, 256>>>(w1, w2);
    prep_glu<<<780, 256>>>(gw, gb);

    // convs as implicit-im2col GEMMs -> pre-activation buffers
    gemm_tf32<1><<<dim3(1, 1500, 1), 256>>>(
        data, 0, 0, 0, w1r, 128, 0, 0, c1buf, 128, 0, 0,
        nullptr, 0, 0, MCONV, 192, 1, Td);
    gemm_tf32<1><<<dim3(1, 1500, 1), 256>>>(
        od, 0, 0, 0, w2r, 128, 0, 0, c2buf, 128, 0, 0,
        nullptr, 0, 0, MCONV, 320, 1, T0d);
    conv_epi<<<48000, 256>>>(b1, b2, out);

    // wingY[w] = adj[:, :2N] @ xr[w*N : w*N+2N]
    gemm_tf32<0><<<dim3(4, 24, 8), 256>>>(
        adj, 3 * Nn, 0, 0, xr, 512, NB, 0, wingY, 512, NB, 0,
        nullptr, 0, 0, Nn, 2 * Nn, 1, 0);

    for (int k = 0; k < 3; ++k) {
        const float* dsrc = (k == 0) ? (xr + 2 * NB) : dK[k - 1];
        // y = adj[:, 2N:] @ d + wingY
        gemm_tf32<0><<<dim3(4, 24, 8), 256>>>(
            adj + 2 * Nn, 3 * Nn, 0, 0, dsrc, 512, NB, 0, ybuf, 512, NB, 0,
            wingY, NB, 0, Nn, Nn, 1, 0);
        // fused GLU: d_k = (y@Wl + bl) * sigm(y@Wr + br), batched over z=(w*8+b)
        gemm_tf32<2><<<dim3(1, 24, 64), 256>>>(
            ybuf, 512, NB, 64,
            gwr + k * 64 * 128, 128, 3 * 64 * 128, 0,
            dK[k], 512, NB, 64,
            gbr + k * 128, 3 * 128, 0, Nn, 64, 8, 0);
    }

    final_add<<<48000, 256>>>(out);
}

// round 16
// speedup vs baseline: 1.3356x; 1.0514x over previous
#include <cuda_runtime.h>
#include <math.h>

namespace cfg {
constexpr int Bb = 8, Td = 10, T0d = 12, Nn = 3000, Cc = 64, Wd = 8;
constexpr int BC = Bb * Cc;            // 512
constexpr int MCONV = Bb * Wd * Nn;    // 192000 = 1500*128
}
using namespace cfg;

// ---------------- scratch (device globals; no allocations) ----------------
__device__ float g_xr[Td * Nn * BC];
__device__ float g_wingY[Wd * Nn * BC];
__device__ float g_ybuf[Wd * Nn * BC];
__device__ float g_d0[Wd * Nn * BC];
__device__ float g_d1[Wd * Nn * BC];
__device__ float g_d2[Wd * Nn * BC];
__device__ float g_c1buf[MCONV * 128];
__device__ float g_c2buf[MCONV * 128];
__device__ float g_w1r[192 * 128];
__device__ float g_w2r[320 * 128];
__device__ float g_gwr[Wd * 3 * 64 * 128];
__device__ float g_gbr[Wd * 3 * 128];

__device__ __forceinline__ unsigned f2t(float x) {
    unsigned u; asm("cvt.rna.tf32.f32 %0, %1;" : "=r"(u) : "f"(x)); return u;
}
__device__ __forceinline__ float sigm(float x) { return 1.f / (1.f + expf(-x)); }
__device__ __forceinline__ void mma8(float* c, const unsigned* a, unsigned b0, unsigned b1) {
    asm volatile("mma.sync.aligned.m16n8k8.row.col.f32.tf32.tf32.f32 "
                 "{%0,%1,%2,%3},{%4,%5,%6,%7},{%8,%9},{%0,%1,%2,%3};\n"
                 : "+f"(c[0]), "+f"(c[1]), "+f"(c[2]), "+f"(c[3])
                 : "r"(a[0]), "r"(a[1]), "r"(a[2]), "r"(a[3]), "r"(b0), "r"(b1));
}

// ---------------- prep ----------------
__global__ void prep_x(const float* __restrict__ data, const float* __restrict__ temb,
                       const float* __restrict__ semb) {
    int idx = blockIdx.x * blockDim.x + threadIdx.x;
    if (idx >= Td * Nn * BC / 4) return;
    int c4 = idx & 15, rem = idx >> 4;
    int b = rem & 7; rem >>= 3;
    int n = rem % Nn, t = rem / Nn;
    float4 dv = *(const float4*)(data + ((size_t)((b * Td + t) * Nn + n)) * 64 + c4 * 4);
    float4 tv = *(const float4*)(temb + t * 64 + c4 * 4);
    float4 sv = *(const float4*)(semb + (size_t)n * 64 + c4 * 4);
    float4 o = {dv.x + tv.x + sv.x, dv.y + tv.y + sv.y, dv.z + tv.z + sv.z, dv.w + tv.w + sv.w};
    *(float4*)(g_xr + (size_t)idx * 4) = o;
}

__global__ void prep_w(const float* __restrict__ w1, const float* __restrict__ w2) {
    int idx = blockIdx.x * blockDim.x + threadIdx.x;
    if (idx < 192 * 128) {
        int oc = idx & 127, kk = idx >> 7, c = kk & 63, ms = kk >> 6;
        g_w1r[idx] = w1[(oc * 64 + c) * 3 + ms];
    } else if (idx < 192 * 128 + 320 * 128) {
        int j = idx - 192 * 128;
        int oc = j & 127, kk = j >> 7, c = kk & 63, ms = kk >> 6;
        g_w2r[j] = w2[(oc * 64 + c) * 5 + ms];
    }
}

// permute glu weights/bias so that (lhs,rhs) gate pairs are adjacent columns
__global__ void prep_glu(const float* __restrict__ gw, const float* __restrict__ gb) {
    int idx = blockIdx.x * blockDim.x + threadIdx.x;
    const int NW = Wd * 3 * 64 * 128;
    if (idx < NW) {
        int j = idx & 127, rc = idx >> 7;  // rc = (w*3+k)*64 + c
        g_gwr[idx] = gw[(size_t)rc * 128 + (j >> 1) + (j & 1) * 64];
    } else if (idx < NW + Wd * 3 * 128) {
        int t = idx - NW;
        int j = t & 127, wk = t >> 7;
        g_gbr[t] = gb[wk * 128 + (j >> 1) + (j & 1) * 64];
    }
}

// ---------------- tf32 GEMM: C = A(MxK) @ B(KxN), 128x128x16 block, 4 warps 64x64 ----
// MODE 0: plain (+Add if AddP)   MODE 1: conv im2col A-gather
// MODE 2: GLU epilogue: (zl,zr) adjacent cols; d=(zl+bl)*sigm(zr+br) at col nc>>1
template <int MODE>
__global__ __launch_bounds__(128, 2) void gemm_tf32(
    const float* __restrict__ A, long long lda, long long sAo, long long sAi,
    const float* __restrict__ Bm, long long ldb, long long sBo, long long sBi,
    float* __restrict__ Cm, long long ldc, long long sCo, long long sCi,
    const float* __restrict__ AddP, long long sDo, long long sDi,
    int M, int Kd, int binner, int Tdim) {
    // As: [m][k] stride 20 -> frag loads bank = (20*(lane>>2) + (lane&3)) distinct
    // Bs: [k][n] stride 136 -> frag loads bank = (8*(lane&3) + (lane>>2)) distinct
    __shared__ __align__(16) unsigned As[2][128][20];
    __shared__ __align__(16) unsigned Bs[2][16][136];

    const int z = blockIdx.z, zo = z / binner, zi = z - zo * binner;
    A += zo * sAo + zi * sAi;
    Bm += zo * sBo + zi * sBi;
    Cm += zo * sCo + zi * sCi;
    const float* Ad = AddP ? (AddP + zo * sDo + zi * sDi) : nullptr;

    const int tid = threadIdx.x, lane = tid & 31, warp = tid >> 5;
    const int wm = warp >> 1, wn = warp & 1;          // 2x2 warps, 64x64 each
    const int m0 = blockIdx.y * 128, n0 = blockIdx.x * 128;
    const int aRow = tid >> 2, aKq = tid & 3;          // A: 4 iters of 32 rows
    const int bKk = tid >> 5, bNq = tid & 31;          // B: 4 iters of 4 k-rows

    long long baseA[4];
    if (MODE == 1) {
#pragma unroll
        for (int it = 0; it < 4; ++it) {
            int m = m0 + aRow + it * 32;
            int b = m / (Wd * Nn), rem = m - b * (Wd * Nn);
            int w = rem / Nn, n = rem - w * Nn;
            baseA[it] = ((long long)((b * Tdim + w) * Nn + n)) * 64;
        }
    }

    float acc[4][8][4];
#pragma unroll
    for (int i = 0; i < 4; i++)
#pragma unroll
        for (int j = 0; j < 8; j++)
#pragma unroll
            for (int q = 0; q < 4; q++) acc[i][j][q] = 0.f;

    float aReg[4][4], bReg[4][4];
    const int ntiles = (Kd + 15) >> 4;

    auto LOAD = [&](int kt) {
        const int k0 = kt << 4;
        const int kg = k0 + aKq * 4;
#pragma unroll
        for (int it = 0; it < 4; ++it) {
            if (MODE == 1) {
                const int ms = kg >> 6, cc = kg & 63;
                float4 v = *(const float4*)(A + baseA[it] + (long long)ms * (Nn * 64) + cc);
                aReg[it][0] = v.x; aReg[it][1] = v.y; aReg[it][2] = v.z; aReg[it][3] = v.w;
            } else {
                const int mg = m0 + aRow + it * 32;
                if (mg < M && kg + 4 <= Kd) {
                    float4 v = *(const float4*)(A + (long long)mg * lda + kg);
                    aReg[it][0] = v.x; aReg[it][1] = v.y; aReg[it][2] = v.z; aReg[it][3] = v.w;
                } else {
#pragma unroll
                    for (int j = 0; j < 4; j++)
                        aReg[it][j] = (mg < M && kg + j < Kd) ? A[(long long)mg * lda + kg + j] : 0.f;
                }
            }
        }
#pragma unroll
        for (int it = 0; it < 4; ++it) {
            const int kr = k0 + bKk + it * 4;
            if (kr < Kd) {
                float4 v = *(const float4*)(Bm + (long long)kr * ldb + n0 + bNq * 4);
                bReg[it][0] = v.x; bReg[it][1] = v.y; bReg[it][2] = v.z; bReg[it][3] = v.w;
            } else {
                bReg[it][0] = bReg[it][1] = bReg[it][2] = bReg[it][3] = 0.f;
            }
        }
    };
    auto STOREs = [&](int buf) {
#pragma unroll
        for (int it = 0; it < 4; ++it) {
            uint4 p = {f2t(aReg[it][0]), f2t(aReg[it][1]), f2t(aReg[it][2]), f2t(aReg[it][3])};
            *(uint4*)&As[buf][aRow + it * 32][aKq * 4] = p;
        }
#pragma unroll
        for (int it = 0; it < 4; ++it) {
            uint4 p = {f2t(bReg[it][0]), f2t(bReg[it][1]), f2t(bReg[it][2]), f2t(bReg[it][3])};
            *(uint4*)&Bs[buf][bKk + it * 4][bNq * 4] = p;
        }
    };
    auto COMP = [&](int buf) {
#pragma unroll
        for (int ks = 0; ks < 2; ++ks) {
            const int kb = ks * 8 + (lane & 3);
            unsigned afr[4][4];
#pragma unroll
            for (int mt = 0; mt < 4; ++mt) {
                const int mr = wm * 64 + mt * 16 + (lane >> 2);
                afr[mt][0] = As[buf][mr][kb];
                afr[mt][1] = As[buf][mr + 8][kb];
                afr[mt][2] = As[buf][mr][kb + 4];
                afr[mt][3] = As[buf][mr + 8][kb + 4];
            }
#pragma unroll
            for (int nt = 0; nt < 8; ++nt) {
                const int nc = wn * 64 + nt * 8 + (lane >> 2);
                const unsigned b0 = Bs[buf][kb][nc];
                const unsigned b1 = Bs[buf][kb + 4][nc];
#pragma unroll
                for (int mt = 0; mt < 4; ++mt) mma8(acc[mt][nt], afr[mt], b0, b1);
            }
        }
    };

    LOAD(0);
    STOREs(0);
    __syncthreads();
    for (int kt = 0; kt < ntiles; ++kt) {
        const int buf = kt & 1;
        if (kt + 1 < ntiles) LOAD(kt + 1);
        COMP(buf);
        if (kt + 1 < ntiles) STOREs(buf ^ 1);
        __syncthreads();
    }

#pragma unroll
    for (int mt = 0; mt < 4; ++mt) {
#pragma unroll
        for (int half = 0; half < 2; ++half) {
            const int mr = m0 + wm * 64 + mt * 16 + (lane >> 2) + half * 8;
            if (mr >= M) continue;
#pragma unroll
            for (int nt = 0; nt < 8; ++nt) {
                const int nc = n0 + wn * 64 + nt * 8 + (lane & 3) * 2;
                float v0 = acc[mt][nt][half * 2 + 0];
                float v1 = acc[mt][nt][half * 2 + 1];
                if (MODE == 2) {
                    float2 bb = *(const float2*)(Ad + nc);
                    float d = (v0 + bb.x) * sigm(v1 + bb.y);
                    Cm[(long long)mr * ldc + (nc >> 1)] = d;
                } else {
                    if (Ad) {
                        float2 av = *(const float2*)(Ad + (long long)mr * ldc + nc);
                        v0 += av.x; v1 += av.y;
                    }
                    float2 ov = {v0, v1};
                    *(float2*)(Cm + (long long)mr * ldc + nc) = ov;
                }
            }
        }
    }
}

// ---------------- elementwise ----------------
__global__ void conv_epi(const float* __restrict__ c1b, const float* __restrict__ c2b,
                         float* __restrict__ out) {
    int idx = blockIdx.x * blockDim.x + threadIdx.x;
    if (idx >= MCONV * 64) return;
    int c = idx & 63;
    long long r = idx >> 6;
    float L1 = g_c1buf[r * 128 + c] + c1b[c];
    float R1 = g_c1buf[r * 128 + 64 + c] + c1b[64 + c];
    float L2 = g_c2buf[r * 128 + c] + c2b[c];
    float R2 = g_c2buf[r * 128 + 64 + c] + c2b[64 + c];
    out[idx] = sigm(L1) * R1 + sigm(L2) * R2;
}

__global__ void final_add(float* __restrict__ out) {
    int idx = blockIdx.x * blockDim.x + threadIdx.x;
    if (idx >= Bb * Wd * Nn * 64) return;
    int c = idx & 63;
    int r = idx >> 6;                       // (b*W+w)*N + n
    int bw = r / Nn, n = r - bw * Nn;
    int w = bw & 7, b = bw >> 3;
    long long mi = (long long)(w * Nn + n) * 512 + b * 64 + c;
    long long xi = (long long)((w + 2) * Nn + n) * 512 + b * 64 + c;
    float mx = fmaxf(fmaxf(g_d0[mi], g_d1[mi]), g_d2[mi]);
    out[idx] += mx + g_xr[xi];
}

// ---------------- launch ----------------
extern "C" void kernel_launch(void* const* d_in, const int* in_sizes, int n_in,
                              void* d_out, int out_size) {
    const float* od   = (const float*)d_in[0];
    const float* data = (const float*)d_in[1];
    const float* adj  = (const float*)d_in[2];
    const float* w1   = (const float*)d_in[3];
    const float* b1   = (const float*)d_in[4];
    const float* w2   = (const float*)d_in[5];
    const float* b2   = (const float*)d_in[6];
    const float* temb = (const float*)d_in[7];
    const float* semb = (const float*)d_in[8];
    const float* gw   = (const float*)d_in[9];
    const float* gb   = (const float*)d_in[10];
    float* out = (float*)d_out;

    float *xr, *wingY, *ybuf, *c1buf, *c2buf, *w1r, *w2r, *gwr, *gbr;
    float* dK[3];
    cudaGetSymbolAddress((void**)&xr, g_xr);
    cudaGetSymbolAddress((void**)&wingY, g_wingY);
    cudaGetSymbolAddress((void**)&ybuf, g_ybuf);
    cudaGetSymbolAddress((void**)&dK[0], g_d0);
    cudaGetSymbolAddress((void**)&dK[1], g_d1);
    cudaGetSymbolAddress((void**)&dK[2], g_d2);
    cudaGetSymbolAddress((void**)&c1buf, g_c1buf);
    cudaGetSymbolAddress((void**)&c2buf, g_c2buf);
    cudaGetSymbolAddress((void**)&w1r, g_w1r);
    cudaGetSymbolAddress((void**)&w2r, g_w2r);
    cudaGetSymbolAddress((void**)&gwr, g_gwr);
    cudaGetSymbolAddress((void**)&gbr, g_gbr);

    const long long NB = (long long)Nn * 512;   // per-window row block in xr layout

    prep_x<<<15000, 256>>>(data, temb, semb);
    prep_w<<<256, 256>>>(w1, w2);
    prep_glu<<<780, 256>>>(gw, gb);

    // convs as implicit-im2col GEMMs -> pre-activation buffers
    gemm_tf32<1><<<dim3(1, 1500, 1), 128>>>(
        data, 0, 0, 0, w1r, 128, 0, 0, c1buf, 128, 0, 0,
        nullptr, 0, 0, MCONV, 192, 1, Td);
    gemm_tf32<1><<<dim3(1, 1500, 1), 128>>>(
        od, 0, 0, 0, w2r, 128, 0, 0, c2buf, 128, 0, 0,
        nullptr, 0, 0, MCONV, 320, 1, T0d);
    conv_epi<<<48000, 256>>>(b1, b2, out);

    // wingY[w] = adj[:, :2N] @ xr[w*N : w*N+2N]
    gemm_tf32<0><<<dim3(4, 24, 8), 128>>>(
        adj, 3 * Nn, 0, 0, xr, 512, NB, 0, wingY, 512, NB, 0,
        nullptr, 0, 0, Nn, 2 * Nn, 1, 0);

    for (int k = 0; k < 3; ++k) {
        const float* dsrc = (k == 0) ? (xr + 2 * NB) : dK[k - 1];
        // y = adj[:, 2N:] @ d + wingY
        gemm_tf32<0><<<dim3(4, 24, 8), 128>>>(
            adj + 2 * Nn, 3 * Nn, 0, 0, dsrc, 512, NB, 0, ybuf, 512, NB, 0,
            wingY, NB, 0, Nn, Nn, 1, 0);
        // fused GLU: d_k = (y@Wl + bl) * sigm(y@Wr + br), batched over z=(w*8+b)
        gemm_tf32<2><<<dim3(1, 24, 64), 128>>>(
            ybuf, 512, NB, 64,
            gwr + k * 64 * 128, 128, 3 * 64 * 128, 0,
            dK[k], 512, NB, 64,
            gbr + k * 128, 3 * 128, 0, Nn, 64, 8, 0);
    }

    final_add<<<48000, 256>>>(out);
}

// round 17
// speedup vs baseline: 1.3356x; 1.0000x over previous
#include <cuda_runtime.h>
#include <math.h>

namespace cfg {
constexpr int Bb = 8, Td = 10, T0d = 12, Nn = 3000, Cc = 64, Wd = 8;
constexpr int BC = Bb * Cc;            // 512
constexpr int MCONV = Bb * Wd * Nn;    // 192000 = 1500*128
}
using namespace cfg;

// ---------------- scratch (device globals; no allocations) ----------------
__device__ float g_xr[Td * Nn * BC];
__device__ float g_wingY[Wd * Nn * BC];
__device__ float g_ybuf[Wd * Nn * BC];
__device__ float g_d0[Wd * Nn * BC];
__device__ float g_d1[Wd * Nn * BC];
__device__ float g_d2[Wd * Nn * BC];
__device__ float g_c1buf[MCONV * 128];
__device__ float g_c2buf[MCONV * 128];
__device__ float g_w1r[192 * 128];
__device__ float g_w2r[320 * 128];
__device__ float g_gwr[Wd * 3 * 64 * 128];
__device__ float g_gbr[Wd * 3 * 128];

__device__ __forceinline__ unsigned f2t(float x) {
    unsigned u; asm("cvt.rna.tf32.f32 %0, %1;" : "=r"(u) : "f"(x)); return u;
}
__device__ __forceinline__ float sigm(float x) { return 1.f / (1.f + expf(-x)); }
__device__ __forceinline__ void mma8(float* c, const unsigned* a, unsigned b0, unsigned b1) {
    asm volatile("mma.sync.aligned.m16n8k8.row.col.f32.tf32.tf32.f32 "
                 "{%0,%1,%2,%3},{%4,%5,%6,%7},{%8,%9},{%0,%1,%2,%3};\n"
                 : "+f"(c[0]), "+f"(c[1]), "+f"(c[2]), "+f"(c[3])
                 : "r"(a[0]), "r"(a[1]), "r"(a[2]), "r"(a[3]), "r"(b0), "r"(b1));
}

// ---------------- prep ----------------
__global__ void prep_x(const float* __restrict__ data, const float* __restrict__ temb,
                       const float* __restrict__ semb) {
    int idx = blockIdx.x * blockDim.x + threadIdx.x;
    if (idx >= Td * Nn * BC / 4) return;
    int c4 = idx & 15, rem = idx >> 4;
    int b = rem & 7; rem >>= 3;
    int n = rem % Nn, t = rem / Nn;
    float4 dv = *(const float4*)(data + ((size_t)((b * Td + t) * Nn + n)) * 64 + c4 * 4);
    float4 tv = *(const float4*)(temb + t * 64 + c4 * 4);
    float4 sv = *(const float4*)(semb + (size_t)n * 64 + c4 * 4);
    float4 o = {dv.x + tv.x + sv.x, dv.y + tv.y + sv.y, dv.z + tv.z + sv.z, dv.w + tv.w + sv.w};
    *(float4*)(g_xr + (size_t)idx * 4) = o;
}

__global__ void prep_w(const float* __restrict__ w1, const float* __restrict__ w2) {
    int idx = blockIdx.x * blockDim.x + threadIdx.x;
    if (idx < 192 * 128) {
        int oc = idx & 127, kk = idx >> 7, c = kk & 63, ms = kk >> 6;
        g_w1r[idx] = w1[(oc * 64 + c) * 3 + ms];
    } else if (idx < 192 * 128 + 320 * 128) {
        int j = idx - 192 * 128;
        int oc = j & 127, kk = j >> 7, c = kk & 63, ms = kk >> 6;
        g_w2r[j] = w2[(oc * 64 + c) * 5 + ms];
    }
}

// permute glu weights/bias so that (lhs,rhs) gate pairs are adjacent columns
__global__ void prep_glu(const float* __restrict__ gw, const float* __restrict__ gb) {
    int idx = blockIdx.x * blockDim.x + threadIdx.x;
    const int NW = Wd * 3 * 64 * 128;
    if (idx < NW) {
        int j = idx & 127, rc = idx >> 7;  // rc = (w*3+k)*64 + c
        g_gwr[idx] = gw[(size_t)rc * 128 + (j >> 1) + (j & 1) * 64];
    } else if (idx < NW + Wd * 3 * 128) {
        int t = idx - NW;
        int j = t & 127, wk = t >> 7;
        g_gbr[t] = gb[wk * 128 + (j >> 1) + (j & 1) * 64];
    }
}

// ---------------- tf32 GEMM: C = A(MxK) @ B(KxN), 128x128x16 block, 4 warps 64x64 ----
// MODE 0: plain (+Add if AddP)   MODE 1: conv im2col A-gather
// MODE 2: GLU epilogue: (zl,zr) adjacent cols; d=(zl+bl)*sigm(zr+br) at col nc>>1
template <int MODE>
__global__ __launch_bounds__(128, 2) void gemm_tf32(
    const float* __restrict__ A, long long lda, long long sAo, long long sAi,
    const float* __restrict__ Bm, long long ldb, long long sBo, long long sBi,
    float* __restrict__ Cm, long long ldc, long long sCo, long long sCi,
    const float* __restrict__ AddP, long long sDo, long long sDi,
    int M, int Kd, int binner, int Tdim) {
    // As: [m][k] stride 20 -> frag loads bank = (20*(lane>>2) + (lane&3)) distinct
    // Bs: [k][n] stride 136 -> frag loads bank = (8*(lane&3) + (lane>>2)) distinct
    __shared__ __align__(16) unsigned As[2][128][20];
    __shared__ __align__(16) unsigned Bs[2][16][136];

    const int z = blockIdx.z, zo = z / binner, zi = z - zo * binner;
    A += zo * sAo + zi * sAi;
    Bm += zo * sBo + zi * sBi;
    Cm += zo * sCo + zi * sCi;
    const float* Ad = AddP ? (AddP + zo * sDo + zi * sDi) : nullptr;

    const int tid = threadIdx.x, lane = tid & 31, warp = tid >> 5;
    const int wm = warp >> 1, wn = warp & 1;          // 2x2 warps, 64x64 each
    const int m0 = blockIdx.y * 128, n0 = blockIdx.x * 128;
    const int aRow = tid >> 2, aKq = tid & 3;          // A: 4 iters of 32 rows
    const int bKk = tid >> 5, bNq = tid & 31;          // B: 4 iters of 4 k-rows

    long long baseA[4];
    if (MODE == 1) {
#pragma unroll
        for (int it = 0; it < 4; ++it) {
            int m = m0 + aRow + it * 32;
            int b = m / (Wd * Nn), rem = m - b * (Wd * Nn);
            int w = rem / Nn, n = rem - w * Nn;
            baseA[it] = ((long long)((b * Tdim + w) * Nn + n)) * 64;
        }
    }

    float acc[4][8][4];
#pragma unroll
    for (int i = 0; i < 4; i++)
#pragma unroll
        for (int j = 0; j < 8; j++)
#pragma unroll
            for (int q = 0; q < 4; q++) acc[i][j][q] = 0.f;

    float aReg[4][4], bReg[4][4];
    const int ntiles = (Kd + 15) >> 4;

    auto LOAD = [&](int kt) {
        const int k0 = kt << 4;
        const int kg = k0 + aKq * 4;
#pragma unroll
        for (int it = 0; it < 4; ++it) {
            if (MODE == 1) {
                const int ms = kg >> 6, cc = kg & 63;
                float4 v = *(const float4*)(A + baseA[it] + (long long)ms * (Nn * 64) + cc);
                aReg[it][0] = v.x; aReg[it][1] = v.y; aReg[it][2] = v.z; aReg[it][3] = v.w;
            } else {
                const int mg = m0 + aRow + it * 32;
                if (mg < M && kg + 4 <= Kd) {
                    float4 v = *(const float4*)(A + (long long)mg * lda + kg);
                    aReg[it][0] = v.x; aReg[it][1] = v.y; aReg[it][2] = v.z; aReg[it][3] = v.w;
                } else {
#pragma unroll
                    for (int j = 0; j < 4; j++)
                        aReg[it][j] = (mg < M && kg + j < Kd) ? A[(long long)mg * lda + kg + j] : 0.f;
                }
            }
        }
#pragma unroll
        for (int it = 0; it < 4; ++it) {
            const int kr = k0 + bKk + it * 4;
            if (kr < Kd) {
                float4 v = *(const float4*)(Bm + (long long)kr * ldb + n0 + bNq * 4);
                bReg[it][0] = v.x; bReg[it][1] = v.y; bReg[it][2] = v.z; bReg[it][3] = v.w;
            } else {
                bReg[it][0] = bReg[it][1] = bReg[it][2] = bReg[it][3] = 0.f;
            }
        }
    };
    auto STOREs = [&](int buf) {
#pragma unroll
        for (int it = 0; it < 4; ++it) {
            uint4 p = {f2t(aReg[it][0]), f2t(aReg[it][1]), f2t(aReg[it][2]), f2t(aReg[it][3])};
            *(uint4*)&As[buf][aRow + it * 32][aKq * 4] = p;
        }
#pragma unroll
        for (int it = 0; it < 4; ++it) {
            uint4 p = {f2t(bReg[it][0]), f2t(bReg[it][1]), f2t(bReg[it][2]), f2t(bReg[it][3])};
            *(uint4*)&Bs[buf][bKk + it * 4][bNq * 4] = p;
        }
    };
    auto COMP = [&](int buf) {
#pragma unroll
        for (int ks = 0; ks < 2; ++ks) {
            const int kb = ks * 8 + (lane & 3);
            unsigned afr[4][4];
#pragma unroll
            for (int mt = 0; mt < 4; ++mt) {
                const int mr = wm * 64 + mt * 16 + (lane >> 2);
                afr[mt][0] = As[buf][mr][kb];
                afr[mt][1] = As[buf][mr + 8][kb];
                afr[mt][2] = As[buf][mr][kb + 4];
                afr[mt][3] = As[buf][mr + 8][kb + 4];
            }
#pragma unroll
            for (int nt = 0; nt < 8; ++nt) {
                const int nc = wn * 64 + nt * 8 + (lane >> 2);
                const unsigned b0 = Bs[buf][kb][nc];
                const unsigned b1 = Bs[buf][kb + 4][nc];
#pragma unroll
                for (int mt = 0; mt < 4; ++mt) mma8(acc[mt][nt], afr[mt], b0, b1);
            }
        }
    };

    LOAD(0);
    STOREs(0);
    __syncthreads();
    for (int kt = 0; kt < ntiles; ++kt) {
        const int buf = kt & 1;
        if (kt + 1 < ntiles) LOAD(kt + 1);
        COMP(buf);
        if (kt + 1 < ntiles) STOREs(buf ^ 1);
        __syncthreads();
    }

#pragma unroll
    for (int mt = 0; mt < 4; ++mt) {
#pragma unroll
        for (int half = 0; half < 2; ++half) {
            const int mr = m0 + wm * 64 + mt * 16 + (lane >> 2) + half * 8;
            if (mr >= M) continue;
#pragma unroll
            for (int nt = 0; nt < 8; ++nt) {
                const int nc = n0 + wn * 64 + nt * 8 + (lane & 3) * 2;
                float v0 = acc[mt][nt][half * 2 + 0];
                float v1 = acc[mt][nt][half * 2 + 1];
                if (MODE == 2) {
                    float2 bb = *(const float2*)(Ad + nc);
                    float d = (v0 + bb.x) * sigm(v1 + bb.y);
                    Cm[(long long)mr * ldc + (nc >> 1)] = d;
                } else {
                    if (Ad) {
                        float2 av = *(const float2*)(Ad + (long long)mr * ldc + nc);
                        v0 += av.x; v1 += av.y;
                    }
                    float2 ov = {v0, v1};
                    *(float2*)(Cm + (long long)mr * ldc + nc) = ov;
                }
            }
        }
    }
}

// ---------------- elementwise ----------------
__global__ void conv_epi(const float* __restrict__ c1b, const float* __restrict__ c2b,
                         float* __restrict__ out) {
    int idx = blockIdx.x * blockDim.x + threadIdx.x;
    if (idx >= MCONV * 64) return;
    int c = idx & 63;
    long long r = idx >> 6;
    float L1 = g_c1buf[r * 128 + c] + c1b[c];
    float R1 = g_c1buf[r * 128 + 64 + c] + c1b[64 + c];
    float L2 = g_c2buf[r * 128 + c] + c2b[c];
    float R2 = g_c2buf[r * 128 + 64 + c] + c2b[64 + c];
    out[idx] = sigm(L1) * R1 + sigm(L2) * R2;
}

__global__ void final_add(float* __restrict__ out) {
    int idx = blockIdx.x * blockDim.x + threadIdx.x;
    if (idx >= Bb * Wd * Nn * 64) return;
    int c = idx & 63;
    int r = idx >> 6;                       // (b*W+w)*N + n
    int bw = r / Nn, n = r - bw * Nn;
    int w = bw & 7, b = bw >> 3;
    long long mi = (long long)(w * Nn + n) * 512 + b * 64 + c;
    long long xi = (long long)((w + 2) * Nn + n) * 512 + b * 64 + c;
    float mx = fmaxf(fmaxf(g_d0[mi], g_d1[mi]), g_d2[mi]);
    out[idx] += mx + g_xr[xi];
}

// ---------------- launch ----------------
extern "C" void kernel_launch(void* const* d_in, const int* in_sizes, int n_in,
                              void* d_out, int out_size) {
    const float* od   = (const float*)d_in[0];
    const float* data = (const float*)d_in[1];
    const float* adj  = (const float*)d_in[2];
    const float* w1   = (const float*)d_in[3];
    const float* b1   = (const float*)d_in[4];
    const float* w2   = (const float*)d_in[5];
    const float* b2   = (const float*)d_in[6];
    const float* temb = (const float*)d_in[7];
    const float* semb = (const float*)d_in[8];
    const float* gw   = (const float*)d_in[9];
    const float* gb   = (const float*)d_in[10];
    float* out = (float*)d_out;

    float *xr, *wingY, *ybuf, *c1buf, *c2buf, *w1r, *w2r, *gwr, *gbr;
    float* dK[3];
    cudaGetSymbolAddress((void**)&xr, g_xr);
    cudaGetSymbolAddress((void**)&wingY, g_wingY);
    cudaGetSymbolAddress((void**)&ybuf, g_ybuf);
    cudaGetSymbolAddress((void**)&dK[0], g_d0);
    cudaGetSymbolAddress((void**)&dK[1], g_d1);
    cudaGetSymbolAddress((void**)&dK[2], g_d2);
    cudaGetSymbolAddress((void**)&c1buf, g_c1buf);
    cudaGetSymbolAddress((void**)&c2buf, g_c2buf);
    cudaGetSymbolAddress((void**)&w1r, g_w1r);
    cudaGetSymbolAddress((void**)&w2r, g_w2r);
    cudaGetSymbolAddress((void**)&gwr, g_gwr);
    cudaGetSymbolAddress((void**)&gbr, g_gbr);

    const long long NB = (long long)Nn * 512;   // per-window row block in xr layout

    prep_x<<<15000, 256>>>(data, temb, semb);
    prep_w<<<256, 256>>>(w1, w2);
    prep_glu<<<780, 256>>>(gw, gb);

    // convs as implicit-im2col GEMMs -> pre-activation buffers
    gemm_tf32<1><<<dim3(1, 1500, 1), 128>>>(
        data, 0, 0, 0, w1r, 128, 0, 0, c1buf, 128, 0, 0,
        nullptr, 0, 0, MCONV, 192, 1, Td);
    gemm_tf32<1><<<dim3(1, 1500, 1), 128>>>(
        od, 0, 0, 0, w2r, 128, 0, 0, c2buf, 128, 0, 0,
        nullptr, 0, 0, MCONV, 320, 1, T0d);
    conv_epi<<<48000, 256>>>(b1, b2, out);

    // wingY[w] = adj[:, :2N] @ xr[w*N : w*N+2N]
    gemm_tf32<0><<<dim3(4, 24, 8), 128>>>(
        adj, 3 * Nn, 0, 0, xr, 512, NB, 0, wingY, 512, NB, 0,
        nullptr, 0, 0, Nn, 2 * Nn, 1, 0);

    for (int k = 0; k < 3; ++k) {
        const float* dsrc = (k == 0) ? (xr + 2 * NB) : dK[k - 1];
        // y = adj[:, 2N:] @ d + wingY
        gemm_tf32<0><<<dim3(4, 24, 8), 128>>>(
            adj + 2 * Nn, 3 * Nn, 0, 0, dsrc, 512, NB, 0, ybuf, 512, NB, 0,
            wingY, NB, 0, Nn, Nn, 1, 0);
        // fused GLU: d_k = (y@Wl + bl) * sigm(y@Wr + br), batched over z=(w*8+b)
        gemm_tf32<2><<<dim3(1, 24, 64), 128>>>(
            ybuf, 512, NB, 64,
            gwr + k * 64 * 128, 128, 3 * 64 * 128, 0,
            dK[k], 512, NB, 64,
            gbr + k * 128, 3 * 128, 0, Nn, 64, 8, 0);
    }

    final_add<<<48000, 256>>>(out);
}